// round 16
// baseline (speedup 1.0000x reference)
#include <cuda_runtime.h>
#include <cuda_fp16.h>
#include <math.h>
#include <float.h>
#include <stdint.h>

// ---------------------------------------------------------------------------
// Problem constants
// ---------------------------------------------------------------------------
#define DIM    512
#define KLAT   360
#define KP     384          // padded K
#define KHALF  192          // K columns per CTA (cluster rank)
#define MRBF   145
#define TM     64           // t-rows per cluster (both CTAs share rows)
#define DC     32           // D-chunk (halves) -> 64 B rows, SW64
#define NCHUNK (DIM / DC)   // 16
#define NTHREADS 256

// SMEM (bytes). Pipeline: A 2buf x 2half x 4KB = 16KB, B 2buf x 2half x 12KB = 48KB.
#define ABUF(buf, lo)  ((buf) * 8192 + (lo) * 4096)             // 0 .. 16384
#define BBUF(buf, lo)  (16384 + (buf) * 24576 + (lo) * 12288)   // .. 65536
#define SMEM_TOTAL 65536
// Epilogue overlays the pipeline region:
#define OFF_STAGE 0                  // 64 x 196 floats = 50176
#define STAGE_STRIDE 196
#define OFF_REDM  50176              // 2*64 floats
#define OFF_REDS  50688              // 2*64 floats
#define OFF_LM    51200              // 64 floats (for peer reads)
#define OFF_LS    51456              // 64 floats
#define OFF_LL    51712              // 64 floats (global-max-relative sum s_n)
#define OFF_YN    51968              // 192 floats
#define OFF_FLAG  52736              // int flag -> 52740

// Scratch (device globals; no allocation allowed)
__device__ float  g_ynorm[KP];
__device__ __half g_Ysp[2 * KP * DIM];   // hi at [0], lo at [KP*DIM]
__device__ double g_partial[4096];
__device__ int    g_counter;

#define YLO_OFF_U4 (KP * DIM / 8)        // lo offset in uint4 units

// ---------------------------------------------------------------------------
// helpers
// ---------------------------------------------------------------------------
__device__ __forceinline__ uint32_t smem_u32(const void* p) {
    uint32_t a;
    asm("{ .reg .u64 t; cvta.to.shared.u64 t, %1; cvt.u32.u64 %0, t; }"
        : "=r"(a) : "l"(p));
    return a;
}
__device__ __forceinline__ uint32_t swz64(uint32_t off) {
    return off ^ ((off >> 3) & 0x30);
}
__device__ __forceinline__ void ldsm_x4(uint32_t* r, uint32_t addr) {
    asm volatile("ldmatrix.sync.aligned.m8n8.x4.shared.b16 {%0,%1,%2,%3}, [%4];"
                 : "=r"(r[0]), "=r"(r[1]), "=r"(r[2]), "=r"(r[3]) : "r"(addr));
}
__device__ __forceinline__ void mma16816(float* c, const uint32_t* a,
                                         uint32_t b0, uint32_t b1) {
    asm volatile("mma.sync.aligned.m16n8k16.row.col.f32.f16.f16.f32 "
                 "{%0,%1,%2,%3}, {%4,%5,%6,%7}, {%8,%9}, {%0,%1,%2,%3};"
                 : "+f"(c[0]), "+f"(c[1]), "+f"(c[2]), "+f"(c[3])
                 : "r"(a[0]), "r"(a[1]), "r"(a[2]), "r"(a[3]), "r"(b0), "r"(b1));
}
__device__ __forceinline__ void cp_async16(uint32_t dst, const void* src) {
    asm volatile("cp.async.cg.shared.global [%0], [%1], 16;"
                 :: "r"(dst), "l"(src) : "memory");
}
#define CP_COMMIT() asm volatile("cp.async.commit_group;" ::: "memory")
#define CP_WAIT0()  asm volatile("cp.async.wait_group 0;" ::: "memory")
#define CLUSTER_SYNC() do { \
    asm volatile("barrier.cluster.arrive.aligned;" ::: "memory"); \
    asm volatile("barrier.cluster.wait.aligned;" ::: "memory"); \
} while (0)

__device__ __forceinline__ uint32_t cluster_rank() {
    uint32_t r; asm("mov.u32 %0, %%cluster_ctarank;" : "=r"(r)); return r;
}
__device__ __forceinline__ float ld_cluster_f32(uint32_t addr, uint32_t rank) {
    uint32_t ra;
    asm("mapa.shared::cluster.u32 %0, %1, %2;" : "=r"(ra) : "r"(addr), "r"(rank));
    float v;
    asm volatile("ld.shared::cluster.f32 %0, [%1];" : "=f"(v) : "r"(ra) : "memory");
    return v;
}

// ---------------------------------------------------------------------------
// Y = phi @ W with phi computed inline; emit fp16 hi/lo split + ynorm.
// Pad rows zero. Block 0 thread 0 also resets the tail counter (runs before
// the main kernel in-stream, so graph replays are safe).
// ---------------------------------------------------------------------------
__global__ void y_kernel(const float* __restrict__ W) {
    int k = blockIdx.x;
    int t = threadIdx.x;   // 128 threads, 4 cols each
    if (k == 0 && t == 0) g_counter = 0;
    if (k >= KLAT) {
        #pragma unroll
        for (int i = 0; i < 4; i++) {
            g_Ysp[(size_t)k * DIM + t * 4 + i] = __float2half(0.f);
            g_Ysp[(size_t)KP * DIM + (size_t)k * DIM + t * 4 + i] = __float2half(0.f);
        }
        if (t == 0) g_ynorm[k] = 0.0f;
        return;
    }
    __shared__ float phis[MRBF];
    __shared__ double red[128];

    // compute phi row k inline (2 entries per thread)
    {
        int ia = k / 18, ib = k % 18;
        double x0 = -1.0 + ia * (2.0 / 19.0);
        double x1 = -1.0 + ib * (2.0 / 17.0);
        #pragma unroll
        for (int r = 0; r < 2; r++) {
            int m = t + r * 128;
            if (m < MRBF) {
                float val;
                if (m == MRBF - 1) {
                    val = 1.0f;
                } else {
                    int mi = m / 12, mj = m % 12;
                    double step = (2.0 - 2.0 / 12.0) / 11.0;
                    double c0 = -1.0 + 1.0 / 12.0 + mi * step;
                    double c1 = -1.0 + 1.0 / 12.0 + mj * step;
                    double d2 = (x0 - c0) * (x0 - c0) + (x1 - c1) * (x1 - c1);
                    val = (float)exp(-3.0 * d2);
                }
                phis[m] = val;
            }
        }
    }
    __syncthreads();

    float4 acc = make_float4(0.f, 0.f, 0.f, 0.f);
    const float4* W4 = (const float4*)W;
    #pragma unroll 4
    for (int m = 0; m < MRBF; m++) {
        float p = phis[m];
        float4 w = W4[m * (DIM / 4) + t];
        acc.x += p * w.x; acc.y += p * w.y; acc.z += p * w.z; acc.w += p * w.w;
    }
    float a[4] = {acc.x, acc.y, acc.z, acc.w};
    #pragma unroll
    for (int i = 0; i < 4; i++) {
        __half h = __float2half_rn(a[i]);
        __half l = __float2half_rn(a[i] - __half2float(h));
        g_Ysp[(size_t)k * DIM + t * 4 + i] = h;
        g_Ysp[(size_t)KP * DIM + (size_t)k * DIM + t * 4 + i] = l;
    }
    double ss = (double)acc.x * acc.x + (double)acc.y * acc.y +
                (double)acc.z * acc.z + (double)acc.w * acc.w;
    red[t] = ss;
    __syncthreads();
    for (int o = 64; o > 0; o >>= 1) {
        if (t < o) red[t] += red[t + o];
        __syncthreads();
    }
    if (t == 0) g_ynorm[k] = (float)red[0];
}

__global__ void noop_kernel() {}

// ---------------------------------------------------------------------------
// Main fused kernel (R13 mainloop, unchanged): 2-CTA cluster splits K;
// 3 CTAs/SM; warp grid 4(m) x 2(n); j6 tiles in pairs (RAW dist 4).
// Tail: last-done cluster reduces g_partial and writes out[0] (fused final).
// ---------------------------------------------------------------------------
__global__ void __launch_bounds__(NTHREADS, 3) __cluster_dims__(2, 1, 1)
gtm_mma_kernel(const float* __restrict__ t_in, const float* __restrict__ beta,
               float* __restrict__ out, long long out_off, int nrowblk) {
    extern __shared__ char smem[];
    const uint32_t sbase = smem_u32(smem);
    const int tid  = threadIdx.x;
    const int lane = tid & 31;
    const int wid  = tid >> 5;
    const int wr   = wid >> 1;   // 0..3: rows wr*16..+15
    const int wc   = wid & 1;    // 0..1: cols wc*96..+95
    const uint32_t rank = cluster_rank();      // K half

    float acc[12][4];
    #pragma unroll
    for (int j = 0; j < 12; j++)
        #pragma unroll
        for (int c = 0; c < 4; c++) acc[j][c] = 0.0f;

    // ldmatrix per-thread base offsets (UNswizzled; swizzle per access)
    const uint32_t rAb =
        (uint32_t)((wr * 16 + (lane & 15)) * 64 + ((lane >> 4) << 4));
    uint32_t rBb[6];
    #pragma unroll
    for (int j6 = 0; j6 < 6; j6++)
        rBb[j6] = (uint32_t)((wc * 96 + j6 * 16 + (lane & 15)) * 64 + ((lane >> 4) << 4));

    // staging roles
    const int arow = tid >> 2, au = tid & 3;              // A: 1 granule/half
    const float* asrc0 = t_in + ((long long)(blockIdx.x >> 1) * TM + arow) * (long long)DIM
                              + au * 8;
    const uint32_t adst = swz64((uint32_t)(arow * 64 + au * 16));
    // B: 3 granules/half (192 rows x 4 granules = 768 = 3*256)
    const int brow = tid >> 2, bu = tid & 3;
    const uint32_t bdst0 = swz64((uint32_t)(brow * 64 + bu * 16));
    const uint4* bsrc = (const uint4*)g_Ysp + ((size_t)rank * KHALF + brow) * 64 + bu;

    #define STAGE_B(ci, buf) do {                                              \
        uint32_t _dh = sbase + BBUF(buf, 0) + bdst0;                           \
        uint32_t _dl = sbase + BBUF(buf, 1) + bdst0;                           \
        const uint4* _sh = bsrc + (ci) * 4;                                    \
        _Pragma("unroll")                                                      \
        for (int _s = 0; _s < 3; _s++) {                                       \
            cp_async16(_dh + _s * 4096, _sh + (size_t)_s * 4096);              \
            cp_async16(_dl + _s * 4096, _sh + YLO_OFF_U4 + (size_t)_s * 4096); \
        }                                                                      \
    } while (0)

    #define STAGE_A(ci, buf) do {                                              \
        float4 _v0 = *(const float4*)(asrc0 + (ci) * DC);                      \
        float4 _v1 = *(const float4*)(asrc0 + (ci) * DC + 4);                  \
        float _x[8] = {_v0.x,_v0.y,_v0.z,_v0.w,_v1.x,_v1.y,_v1.z,_v1.w};       \
        __align__(16) __half _hi[8], _lo[8];                                   \
        _Pragma("unroll")                                                      \
        for (int _e = 0; _e < 8; _e++) {                                       \
            __half _h = __float2half_rn(_x[_e]);                               \
            _hi[_e] = _h;                                                      \
            _lo[_e] = __float2half_rn(_x[_e] - __half2float(_h));              \
        }                                                                      \
        *(uint4*)(smem + ABUF(buf, 0) + adst) = *(uint4*)_hi;                  \
        *(uint4*)(smem + ABUF(buf, 1) + adst) = *(uint4*)_lo;                  \
    } while (0)

    // prologue: stage chunk 0
    STAGE_B(0, 0); CP_COMMIT();
    STAGE_A(0, 0);

    for (int ci = 0; ci < NCHUNK; ci++) {
        const int buf = ci & 1;
        CP_WAIT0();
        __syncthreads();   // B(ci) visible; all done reading buf^1

        if (ci + 1 < NCHUNK) { STAGE_B(ci + 1, buf ^ 1); CP_COMMIT(); }

        const uint32_t ahi = sbase + ABUF(buf, 0);
        const uint32_t alo = sbase + ABUF(buf, 1);
        const uint32_t bhi = sbase + BBUF(buf, 0);
        const uint32_t blo = sbase + BBUF(buf, 1);

        #pragma unroll
        for (int ks = 0; ks < 2; ks++) {
            const uint32_t ko = (uint32_t)(ks * 32);
            uint32_t ah[4], al[4];
            ldsm_x4(ah, ahi + swz64(rAb + ko));
            ldsm_x4(al, alo + swz64(rAb + ko));
            #pragma unroll
            for (int jp = 0; jp < 3; jp++) {
                const int j0 = 2 * jp, j1 = 2 * jp + 1;
                uint32_t bh0[4], bl0[4], bh1[4], bl1[4];
                ldsm_x4(bh0, bhi + swz64(rBb[j0] + ko));
                ldsm_x4(bl0, blo + swz64(rBb[j0] + ko));
                ldsm_x4(bh1, bhi + swz64(rBb[j1] + ko));
                ldsm_x4(bl1, blo + swz64(rBb[j1] + ko));
                // pass 1: Ahi*Bhi, both tiles (4 independent targets)
                mma16816(acc[2 * j0 + 0], ah, bh0[0], bh0[2]);
                mma16816(acc[2 * j0 + 1], ah, bh0[1], bh0[3]);
                mma16816(acc[2 * j1 + 0], ah, bh1[0], bh1[2]);
                mma16816(acc[2 * j1 + 1], ah, bh1[1], bh1[3]);
                // pass 2: Alo*Bhi
                mma16816(acc[2 * j0 + 0], al, bh0[0], bh0[2]);
                mma16816(acc[2 * j0 + 1], al, bh0[1], bh0[3]);
                mma16816(acc[2 * j1 + 0], al, bh1[0], bh1[2]);
                mma16816(acc[2 * j1 + 1], al, bh1[1], bh1[3]);
                // pass 3: Ahi*Blo
                mma16816(acc[2 * j0 + 0], ah, bl0[0], bl0[2]);
                mma16816(acc[2 * j0 + 1], ah, bl0[1], bl0[3]);
                mma16816(acc[2 * j1 + 0], ah, bl1[0], bl1[2]);
                mma16816(acc[2 * j1 + 1], ah, bl1[1], bl1[3]);
            }
        }
        if (ci + 1 < NCHUNK) STAGE_A(ci + 1, buf ^ 1);
    }
    __syncthreads();

    // ------------------------- epilogue -------------------------
    float* stage = (float*)(smem + OFF_STAGE);
    float* redm  = (float*)(smem + OFF_REDM);
    float* reds  = (float*)(smem + OFF_REDS);
    float* lm    = (float*)(smem + OFF_LM);
    float* ls    = (float*)(smem + OFF_LS);
    float* ll2   = (float*)(smem + OFF_LL);
    float* yns   = (float*)(smem + OFF_YN);
    int*   lastf = (int*)(smem + OFF_FLAG);

    const float b  = beta[0];
    const float bh = 0.5f * b;
    const long long n0 = (long long)(blockIdx.x >> 1) * TM;

    if (tid < KHALF) yns[tid] = g_ynorm[rank * KHALF + tid];
    __syncthreads();

    const int colb = wc * 96 + (lane & 3) * 2;
    const int kbase = rank * KHALF;

    // E = b*dot - bh*ynorm, mask global k >= KLAT
    #pragma unroll
    for (int j = 0; j < 12; j++) {
        int c0 = colb + j * 8;
        float y0 = yns[c0], y1 = yns[c0 + 1];
        bool v0 = (kbase + c0 < KLAT), v1 = (kbase + c0 + 1 < KLAT);
        #pragma unroll
        for (int h = 0; h < 2; h++) {
            float e0 = b * acc[j][2 * h]     - bh * y0;
            float e1 = b * acc[j][2 * h + 1] - bh * y1;
            acc[j][2 * h]     = v0 ? e0 : -1e30f;
            acc[j][2 * h + 1] = v1 ? e1 : -1e30f;
        }
    }

    // local row max over this CTA's 192 cols
    float lmv[2], lsv[2];
    #pragma unroll
    for (int h = 0; h < 2; h++) {
        float m = -FLT_MAX;
        #pragma unroll
        for (int j = 0; j < 12; j++)
            m = fmaxf(m, fmaxf(acc[j][2 * h], acc[j][2 * h + 1]));
        m = fmaxf(m, __shfl_xor_sync(0xffffffffu, m, 1));
        m = fmaxf(m, __shfl_xor_sync(0xffffffffu, m, 2));
        if ((lane & 3) == 0)
            redm[wc * 64 + wr * 16 + h * 8 + (lane >> 2)] = m;
    }
    __syncthreads();

    #pragma unroll
    for (int h = 0; h < 2; h++) {
        int r = wr * 16 + h * 8 + (lane >> 2);
        lmv[h] = fmaxf(redm[r], redm[64 + r]);
    }

    // exp + local row sum (acc becomes p)
    #pragma unroll
    for (int h = 0; h < 2; h++) {
        float s = 0.0f;
        #pragma unroll
        for (int j = 0; j < 12; j++) {
            float p0 = __expf(acc[j][2 * h]     - lmv[h]);
            float p1 = __expf(acc[j][2 * h + 1] - lmv[h]);
            acc[j][2 * h] = p0; acc[j][2 * h + 1] = p1;
            s += p0 + p1;
        }
        s += __shfl_xor_sync(0xffffffffu, s, 1);
        s += __shfl_xor_sync(0xffffffffu, s, 2);
        if ((lane & 3) == 0)
            reds[wc * 64 + wr * 16 + h * 8 + (lane >> 2)] = s;
    }
    __syncthreads();

    #pragma unroll
    for (int h = 0; h < 2; h++) {
        int r = wr * 16 + h * 8 + (lane >> 2);
        lsv[h] = reds[r] + reds[64 + r];
        if (wc == 0 && (lane & 3) == 0) { lm[r] = lmv[h]; ls[r] = lsv[h]; }
    }
    __syncthreads();

    // ---- exchange (m, s) with peer CTA via DSMEM ----
    CLUSTER_SYNC();
    const uint32_t peer = rank ^ 1u;
    float inv[2];
    #pragma unroll
    for (int h = 0; h < 2; h++) {
        int r = wr * 16 + h * 8 + (lane >> 2);
        float pm = ld_cluster_f32(sbase + OFF_LM + r * 4, peer);
        float ps = ld_cluster_f32(sbase + OFF_LS + r * 4, peer);
        float M = fmaxf(lmv[h], pm);
        float stot = lsv[h] * __expf(lmv[h] - M) + ps * __expf(pm - M);
        inv[h] = __expf(lmv[h] - M) / stot;
        // reference semantics: s_n relative to the GLOBAL row max (no M added)
        if (wc == 0 && (lane & 3) == 0)
            ll2[r] = stot;
    }

    // normalized responsibilities -> stage (local 192 cols)
    #pragma unroll
    for (int h = 0; h < 2; h++) {
        int r = wr * 16 + h * 8 + (lane >> 2);
        float* srow = stage + r * STAGE_STRIDE;
        #pragma unroll
        for (int j = 0; j < 12; j++) {
            int c0 = colb + j * 8;
            srow[c0]     = acc[j][2 * h] * inv[h];
            srow[c0 + 1] = acc[j][2 * h + 1] * inv[h];
        }
    }
    __syncthreads();

    // deterministic ll partial (rank 0, warp 0): 64 rows, 2 per lane
    if (rank == 0 && tid < 32) {
        double a = log((double)ll2[lane]) + log((double)ll2[lane + 32]);
        #pragma unroll
        for (int o = 16; o > 0; o >>= 1)
            a += __shfl_xor_sync(0xffffffffu, a, o);
        if (lane == 0) g_partial[blockIdx.x >> 1] = a;
    }

    // coalesced store of this CTA's K-slice of R.T rows
    #pragma unroll
    for (int i = 0; i < 8; i++) {
        int r = wid + i * 8;
        const float* srow = stage + r * STAGE_STRIDE;
        float* orow = out + out_off + (n0 + r) * (long long)KLAT + kbase;
        #pragma unroll
        for (int s = 0; s < 6; s++) {
            int kl = s * 32 + lane;
            if (kbase + kl < KLAT) orow[kl] = srow[kl];
        }
    }

    // peers may still be reading our lm/ls — hold smem until both are done
    CLUSTER_SYNC();

    // ------------- fused final reduction (last-done cluster) -------------
    if (tid == 0) {
        int last = 0;
        if (rank == 0) {
            __threadfence();
            int old = atomicAdd(&g_counter, 1);
            last = (old == nrowblk - 1);
        }
        *lastf = last;
    }
    __syncthreads();
    if (*lastf && wid == 0) {
        __threadfence();
        double a0 = 0.0, a1 = 0.0;
        for (int i = lane; i < nrowblk; i += 64) {
            a0 += g_partial[i];
            a1 += g_partial[i + 32];
        }
        double a = a0 + a1;
        #pragma unroll
        for (int o = 16; o > 0; o >>= 1)
            a += __shfl_xor_sync(0xffffffffu, a, o);
        if (lane == 0) {
            double bd = (double)b;
            double cst = 256.0 * log(bd / (2.0 * M_PI)) - log(360.0);
            double Nrows = (double)nrowblk * TM;
            double ll = (Nrows * cst + a) / Nrows;
            out[0] = (float)(-ll);
        }
    }
    #undef STAGE_A
    #undef STAGE_B
}

// ---------------------------------------------------------------------------
extern "C" void kernel_launch(void* const* d_in, const int* in_sizes, int n_in,
                              void* d_out, int out_size) {
    const float* t    = (const float*)d_in[0];
    const float* W    = (const float*)d_in[1];
    const float* beta = (const float*)d_in[2];
    float* out = (float*)d_out;

    int N = in_sizes[0] / DIM;                                  // 131072
    long long off = (long long)out_size - (long long)N * KLAT;  // scalar slot first
    if (off < 0) off = 0;

    static int smem_set = 0;
    if (!smem_set) {
        cudaFuncSetAttribute(gtm_mma_kernel,
                             cudaFuncAttributeMaxDynamicSharedMemorySize, SMEM_TOTAL);
        smem_set = 1;
    }

    y_kernel<<<KP, 128>>>(W);           // also resets tail counter
    noop_kernel<<<1, 32>>>();
    int nrowblk = N / TM;               // 2048
    gtm_mma_kernel<<<nrowblk * 2, NTHREADS, SMEM_TOTAL>>>(t, beta, out, off, nrowblk);
}

// round 17
// speedup vs baseline: 1.0825x; 1.0825x over previous
#include <cuda_runtime.h>
#include <cuda_fp16.h>
#include <math.h>
#include <float.h>
#include <stdint.h>

// ---------------------------------------------------------------------------
// Problem constants
// ---------------------------------------------------------------------------
#define DIM    512
#define KLAT   360
#define KP     384          // padded K
#define KHALF  192          // K columns per CTA (cluster rank)
#define MRBF   145
#define TM     64           // t-rows per cluster (both CTAs share rows)
#define DC     32           // D-chunk (halves) -> 64 B rows, SW64
#define NCHUNK (DIM / DC)   // 16
#define NTHREADS 256

// SMEM (bytes). Pipeline: A 2buf x 2half x 4KB = 16KB, B 2buf x 2half x 12KB = 48KB.
#define ABUF(buf, lo)  ((buf) * 8192 + (lo) * 4096)             // 0 .. 16384
#define BBUF(buf, lo)  (16384 + (buf) * 24576 + (lo) * 12288)   // .. 65536
#define SMEM_TOTAL 65536
// Epilogue overlays the pipeline region:
#define OFF_STAGE 0                  // 64 x 196 floats = 50176
#define STAGE_STRIDE 196
#define OFF_REDM  50176              // 2*64 floats
#define OFF_REDS  50688              // 2*64 floats
#define OFF_LM    51200              // 64 floats (for peer reads)
#define OFF_LS    51456              // 64 floats
#define OFF_LL    51712              // 64 floats (global-max-relative sum s_n)
#define OFF_YN    51968              // 192 floats -> 52736

// Scratch (device globals; no allocation allowed)
__device__ float  g_phi[KLAT * MRBF];
__device__ float  g_ynorm[KP];
__device__ __half g_Ysp[2 * KP * DIM];   // hi at [0], lo at [KP*DIM]
__device__ double g_partial[4096];

#define YLO_OFF_U4 (KP * DIM / 8)        // lo offset in uint4 units

// ---------------------------------------------------------------------------
// helpers
// ---------------------------------------------------------------------------
__device__ __forceinline__ uint32_t smem_u32(const void* p) {
    uint32_t a;
    asm("{ .reg .u64 t; cvta.to.shared.u64 t, %1; cvt.u32.u64 %0, t; }"
        : "=r"(a) : "l"(p));
    return a;
}
__device__ __forceinline__ uint32_t swz64(uint32_t off) {
    return off ^ ((off >> 3) & 0x30);
}
__device__ __forceinline__ void ldsm_x4(uint32_t* r, uint32_t addr) {
    asm volatile("ldmatrix.sync.aligned.m8n8.x4.shared.b16 {%0,%1,%2,%3}, [%4];"
                 : "=r"(r[0]), "=r"(r[1]), "=r"(r[2]), "=r"(r[3]) : "r"(addr));
}
__device__ __forceinline__ void mma16816(float* c, const uint32_t* a,
                                         uint32_t b0, uint32_t b1) {
    asm volatile("mma.sync.aligned.m16n8k16.row.col.f32.f16.f16.f32 "
                 "{%0,%1,%2,%3}, {%4,%5,%6,%7}, {%8,%9}, {%0,%1,%2,%3};"
                 : "+f"(c[0]), "+f"(c[1]), "+f"(c[2]), "+f"(c[3])
                 : "r"(a[0]), "r"(a[1]), "r"(a[2]), "r"(a[3]), "r"(b0), "r"(b1));
}
__device__ __forceinline__ void cp_async16(uint32_t dst, const void* src) {
    asm volatile("cp.async.cg.shared.global [%0], [%1], 16;"
                 :: "r"(dst), "l"(src) : "memory");
}
#define CP_COMMIT() asm volatile("cp.async.commit_group;" ::: "memory")
#define CP_WAIT0()  asm volatile("cp.async.wait_group 0;" ::: "memory")
#define CLUSTER_SYNC() do { \
    asm volatile("barrier.cluster.arrive.aligned;" ::: "memory"); \
    asm volatile("barrier.cluster.wait.aligned;" ::: "memory"); \
} while (0)

__device__ __forceinline__ uint32_t cluster_rank() {
    uint32_t r; asm("mov.u32 %0, %%cluster_ctarank;" : "=r"(r)); return r;
}
__device__ __forceinline__ float ld_cluster_f32(uint32_t addr, uint32_t rank) {
    uint32_t ra;
    asm("mapa.shared::cluster.u32 %0, %1, %2;" : "=r"(ra) : "r"(addr), "r"(rank));
    float v;
    asm volatile("ld.shared::cluster.f32 %0, [%1];" : "=f"(v) : "r"(ra) : "memory");
    return v;
}

// ---------------------------------------------------------------------------
// phi[k][m] = exp(-3 * ||x_k - c_m||^2)
// ---------------------------------------------------------------------------
__global__ void phi_kernel() {
    int idx = blockIdx.x * blockDim.x + threadIdx.x;
    if (idx >= KLAT * MRBF) return;
    int k = idx / MRBF, m = idx % MRBF;
    float val;
    if (m == MRBF - 1) {
        val = 1.0f;
    } else {
        int ia = k / 18, ib = k % 18;
        double x0 = -1.0 + ia * (2.0 / 19.0);
        double x1 = -1.0 + ib * (2.0 / 17.0);
        int mi = m / 12, mj = m % 12;
        double step = (2.0 - 2.0 / 12.0) / 11.0;
        double c0 = -1.0 + 1.0 / 12.0 + mi * step;
        double c1 = -1.0 + 1.0 / 12.0 + mj * step;
        double d2 = (x0 - c0) * (x0 - c0) + (x1 - c1) * (x1 - c1);
        val = (float)exp(-3.0 * d2);
    }
    g_phi[idx] = val;
}

// ---------------------------------------------------------------------------
// Y = phi @ W ; emit fp16 hi/lo split + ynorm. Pad rows zero.
// ---------------------------------------------------------------------------
__global__ void y_kernel(const float* __restrict__ W) {
    int k = blockIdx.x;
    int t = threadIdx.x;   // 128 threads, 4 cols each
    if (k >= KLAT) {
        #pragma unroll
        for (int i = 0; i < 4; i++) {
            g_Ysp[(size_t)k * DIM + t * 4 + i] = __float2half(0.f);
            g_Ysp[(size_t)KP * DIM + (size_t)k * DIM + t * 4 + i] = __float2half(0.f);
        }
        if (t == 0) g_ynorm[k] = 0.0f;
        return;
    }
    __shared__ float phis[MRBF];
    __shared__ double red[128];
    if (t < MRBF) phis[t] = g_phi[k * MRBF + t];
    if (t + 128 < MRBF) phis[t + 128] = g_phi[k * MRBF + t + 128];
    __syncthreads();

    float4 acc = make_float4(0.f, 0.f, 0.f, 0.f);
    const float4* W4 = (const float4*)W;
    #pragma unroll 4
    for (int m = 0; m < MRBF; m++) {
        float p = phis[m];
        float4 w = W4[m * (DIM / 4) + t];
        acc.x += p * w.x; acc.y += p * w.y; acc.z += p * w.z; acc.w += p * w.w;
    }
    float a[4] = {acc.x, acc.y, acc.z, acc.w};
    #pragma unroll
    for (int i = 0; i < 4; i++) {
        __half h = __float2half_rn(a[i]);
        __half l = __float2half_rn(a[i] - __half2float(h));
        g_Ysp[(size_t)k * DIM + t * 4 + i] = h;
        g_Ysp[(size_t)KP * DIM + (size_t)k * DIM + t * 4 + i] = l;
    }
    double ss = (double)acc.x * acc.x + (double)acc.y * acc.y +
                (double)acc.z * acc.z + (double)acc.w * acc.w;
    red[t] = ss;
    __syncthreads();
    for (int o = 64; o > 0; o >>= 1) {
        if (t < o) red[t] += red[t + o];
        __syncthreads();
    }
    if (t == 0) g_ynorm[k] = (float)red[0];
}

// ---------------------------------------------------------------------------
// Main fused kernel: 2-CTA cluster splits K (192 cols each); 3 CTAs/SM.
// Warp grid 4(m) x 2(n), warp tile 16 x 96; j6 tiles in pairs (RAW dist 4).
// DSMEM (m,s) exchange; ll uses the reference's max-relative log(s).
// (Byte-identical to the R13 516.3us winner.)
// ---------------------------------------------------------------------------
__global__ void __launch_bounds__(NTHREADS, 3) __cluster_dims__(2, 1, 1)
gtm_mma_kernel(const float* __restrict__ t_in, const float* __restrict__ beta,
               float* __restrict__ out, long long out_off) {
    extern __shared__ char smem[];
    const uint32_t sbase = smem_u32(smem);
    const int tid  = threadIdx.x;
    const int lane = tid & 31;
    const int wid  = tid >> 5;
    const int wr   = wid >> 1;   // 0..3: rows wr*16..+15
    const int wc   = wid & 1;    // 0..1: cols wc*96..+95
    const uint32_t rank = cluster_rank();      // K half

    float acc[12][4];
    #pragma unroll
    for (int j = 0; j < 12; j++)
        #pragma unroll
        for (int c = 0; c < 4; c++) acc[j][c] = 0.0f;

    // ldmatrix per-thread base offsets (UNswizzled; swizzle per access)
    const uint32_t rAb =
        (uint32_t)((wr * 16 + (lane & 15)) * 64 + ((lane >> 4) << 4));
    uint32_t rBb[6];
    #pragma unroll
    for (int j6 = 0; j6 < 6; j6++)
        rBb[j6] = (uint32_t)((wc * 96 + j6 * 16 + (lane & 15)) * 64 + ((lane >> 4) << 4));

    // staging roles
    const int arow = tid >> 2, au = tid & 3;              // A: 1 granule/half
    const float* asrc0 = t_in + ((long long)(blockIdx.x >> 1) * TM + arow) * (long long)DIM
                              + au * 8;
    const uint32_t adst = swz64((uint32_t)(arow * 64 + au * 16));
    // B: 3 granules/half (192 rows x 4 granules = 768 = 3*256)
    const int brow = tid >> 2, bu = tid & 3;
    const uint32_t bdst0 = swz64((uint32_t)(brow * 64 + bu * 16));
    const uint4* bsrc = (const uint4*)g_Ysp + ((size_t)rank * KHALF + brow) * 64 + bu;

    #define STAGE_B(ci, buf) do {                                              \
        uint32_t _dh = sbase + BBUF(buf, 0) + bdst0;                           \
        uint32_t _dl = sbase + BBUF(buf, 1) + bdst0;                           \
        const uint4* _sh = bsrc + (ci) * 4;                                    \
        _Pragma("unroll")                                                      \
        for (int _s = 0; _s < 3; _s++) {                                       \
            cp_async16(_dh + _s * 4096, _sh + (size_t)_s * 4096);              \
            cp_async16(_dl + _s * 4096, _sh + YLO_OFF_U4 + (size_t)_s * 4096); \
        }                                                                      \
    } while (0)

    #define STAGE_A(ci, buf) do {                                              \
        float4 _v0 = *(const float4*)(asrc0 + (ci) * DC);                      \
        float4 _v1 = *(const float4*)(asrc0 + (ci) * DC + 4);                  \
        float _x[8] = {_v0.x,_v0.y,_v0.z,_v0.w,_v1.x,_v1.y,_v1.z,_v1.w};       \
        __align__(16) __half _hi[8], _lo[8];                                   \
        _Pragma("unroll")                                                      \
        for (int _e = 0; _e < 8; _e++) {                                       \
            __half _h = __float2half_rn(_x[_e]);                               \
            _hi[_e] = _h;                                                      \
            _lo[_e] = __float2half_rn(_x[_e] - __half2float(_h));              \
        }                                                                      \
        *(uint4*)(smem + ABUF(buf, 0) + adst) = *(uint4*)_hi;                  \
        *(uint4*)(smem + ABUF(buf, 1) + adst) = *(uint4*)_lo;                  \
    } while (0)

    // prologue: stage chunk 0
    STAGE_B(0, 0); CP_COMMIT();
    STAGE_A(0, 0);

    for (int ci = 0; ci < NCHUNK; ci++) {
        const int buf = ci & 1;
        CP_WAIT0();
        __syncthreads();   // B(ci) visible; all done reading buf^1

        if (ci + 1 < NCHUNK) { STAGE_B(ci + 1, buf ^ 1); CP_COMMIT(); }

        const uint32_t ahi = sbase + ABUF(buf, 0);
        const uint32_t alo = sbase + ABUF(buf, 1);
        const uint32_t bhi = sbase + BBUF(buf, 0);
        const uint32_t blo = sbase + BBUF(buf, 1);

        #pragma unroll
        for (int ks = 0; ks < 2; ks++) {
            const uint32_t ko = (uint32_t)(ks * 32);
            uint32_t ah[4], al[4];
            ldsm_x4(ah, ahi + swz64(rAb + ko));
            ldsm_x4(al, alo + swz64(rAb + ko));
            #pragma unroll
            for (int jp = 0; jp < 3; jp++) {
                const int j0 = 2 * jp, j1 = 2 * jp + 1;
                uint32_t bh0[4], bl0[4], bh1[4], bl1[4];
                ldsm_x4(bh0, bhi + swz64(rBb[j0] + ko));
                ldsm_x4(bl0, blo + swz64(rBb[j0] + ko));
                ldsm_x4(bh1, bhi + swz64(rBb[j1] + ko));
                ldsm_x4(bl1, blo + swz64(rBb[j1] + ko));
                // pass 1: Ahi*Bhi, both tiles (4 independent targets)
                mma16816(acc[2 * j0 + 0], ah, bh0[0], bh0[2]);
                mma16816(acc[2 * j0 + 1], ah, bh0[1], bh0[3]);
                mma16816(acc[2 * j1 + 0], ah, bh1[0], bh1[2]);
                mma16816(acc[2 * j1 + 1], ah, bh1[1], bh1[3]);
                // pass 2: Alo*Bhi
                mma16816(acc[2 * j0 + 0], al, bh0[0], bh0[2]);
                mma16816(acc[2 * j0 + 1], al, bh0[1], bh0[3]);
                mma16816(acc[2 * j1 + 0], al, bh1[0], bh1[2]);
                mma16816(acc[2 * j1 + 1], al, bh1[1], bh1[3]);
                // pass 3: Ahi*Blo
                mma16816(acc[2 * j0 + 0], ah, bl0[0], bl0[2]);
                mma16816(acc[2 * j0 + 1], ah, bl0[1], bl0[3]);
                mma16816(acc[2 * j1 + 0], ah, bl1[0], bl1[2]);
                mma16816(acc[2 * j1 + 1], ah, bl1[1], bl1[3]);
            }
        }
        if (ci + 1 < NCHUNK) STAGE_A(ci + 1, buf ^ 1);
    }
    __syncthreads();

    // ------------------------- epilogue -------------------------
    float* stage = (float*)(smem + OFF_STAGE);
    float* redm  = (float*)(smem + OFF_REDM);
    float* reds  = (float*)(smem + OFF_REDS);
    float* lm    = (float*)(smem + OFF_LM);
    float* ls    = (float*)(smem + OFF_LS);
    float* ll2   = (float*)(smem + OFF_LL);
    float* yns   = (float*)(smem + OFF_YN);

    const float b  = beta[0];
    const float bh = 0.5f * b;
    const long long n0 = (long long)(blockIdx.x >> 1) * TM;

    if (tid < KHALF) yns[tid] = g_ynorm[rank * KHALF + tid];
    __syncthreads();

    const int colb = wc * 96 + (lane & 3) * 2;
    const int kbase = rank * KHALF;

    // E = b*dot - bh*ynorm, mask global k >= KLAT
    #pragma unroll
    for (int j = 0; j < 12; j++) {
        int c0 = colb + j * 8;
        float y0 = yns[c0], y1 = yns[c0 + 1];
        bool v0 = (kbase + c0 < KLAT), v1 = (kbase + c0 + 1 < KLAT);
        #pragma unroll
        for (int h = 0; h < 2; h++) {
            float e0 = b * acc[j][2 * h]     - bh * y0;
            float e1 = b * acc[j][2 * h + 1] - bh * y1;
            acc[j][2 * h]     = v0 ? e0 : -1e30f;
            acc[j][2 * h + 1] = v1 ? e1 : -1e30f;
        }
    }

    // local row max over this CTA's 192 cols
    float lmv[2], lsv[2];
    #pragma unroll
    for (int h = 0; h < 2; h++) {
        float m = -FLT_MAX;
        #pragma unroll
        for (int j = 0; j < 12; j++)
            m = fmaxf(m, fmaxf(acc[j][2 * h], acc[j][2 * h + 1]));
        m = fmaxf(m, __shfl_xor_sync(0xffffffffu, m, 1));
        m = fmaxf(m, __shfl_xor_sync(0xffffffffu, m, 2));
        if ((lane & 3) == 0)
            redm[wc * 64 + wr * 16 + h * 8 + (lane >> 2)] = m;
    }
    __syncthreads();

    #pragma unroll
    for (int h = 0; h < 2; h++) {
        int r = wr * 16 + h * 8 + (lane >> 2);
        lmv[h] = fmaxf(redm[r], redm[64 + r]);
    }

    // exp + local row sum (acc becomes p)
    #pragma unroll
    for (int h = 0; h < 2; h++) {
        float s = 0.0f;
        #pragma unroll
        for (int j = 0; j < 12; j++) {
            float p0 = __expf(acc[j][2 * h]     - lmv[h]);
            float p1 = __expf(acc[j][2 * h + 1] - lmv[h]);
            acc[j][2 * h] = p0; acc[j][2 * h + 1] = p1;
            s += p0 + p1;
        }
        s += __shfl_xor_sync(0xffffffffu, s, 1);
        s += __shfl_xor_sync(0xffffffffu, s, 2);
        if ((lane & 3) == 0)
            reds[wc * 64 + wr * 16 + h * 8 + (lane >> 2)] = s;
    }
    __syncthreads();

    #pragma unroll
    for (int h = 0; h < 2; h++) {
        int r = wr * 16 + h * 8 + (lane >> 2);
        lsv[h] = reds[r] + reds[64 + r];
        if (wc == 0 && (lane & 3) == 0) { lm[r] = lmv[h]; ls[r] = lsv[h]; }
    }
    __syncthreads();

    // ---- exchange (m, s) with peer CTA via DSMEM ----
    CLUSTER_SYNC();
    const uint32_t peer = rank ^ 1u;
    float inv[2];
    #pragma unroll
    for (int h = 0; h < 2; h++) {
        int r = wr * 16 + h * 8 + (lane >> 2);
        float pm = ld_cluster_f32(sbase + OFF_LM + r * 4, peer);
        float ps = ld_cluster_f32(sbase + OFF_LS + r * 4, peer);
        float M = fmaxf(lmv[h], pm);
        float stot = lsv[h] * __expf(lmv[h] - M) + ps * __expf(pm - M);
        inv[h] = __expf(lmv[h] - M) / stot;
        // reference semantics: s_n relative to the GLOBAL row max (no M added)
        if (wc == 0 && (lane & 3) == 0)
            ll2[r] = stot;
    }

    // normalized responsibilities -> stage (local 192 cols)
    #pragma unroll
    for (int h = 0; h < 2; h++) {
        int r = wr * 16 + h * 8 + (lane >> 2);
        float* srow = stage + r * STAGE_STRIDE;
        #pragma unroll
        for (int j = 0; j < 12; j++) {
            int c0 = colb + j * 8;
            srow[c0]     = acc[j][2 * h] * inv[h];
            srow[c0 + 1] = acc[j][2 * h + 1] * inv[h];
        }
    }
    __syncthreads();

    // deterministic ll partial (rank 0, warp 0): 64 rows, 2 per lane
    if (rank == 0 && tid < 32) {
        double a = log((double)ll2[lane]) + log((double)ll2[lane + 32]);
        #pragma unroll
        for (int o = 16; o > 0; o >>= 1)
            a += __shfl_xor_sync(0xffffffffu, a, o);
        if (lane == 0) g_partial[blockIdx.x >> 1] = a;
    }

    // coalesced store of this CTA's K-slice of R.T rows
    #pragma unroll
    for (int i = 0; i < 8; i++) {
        int r = wid + i * 8;
        const float* srow = stage + r * STAGE_STRIDE;
        float* orow = out + out_off + (n0 + r) * (long long)KLAT + kbase;
        #pragma unroll
        for (int s = 0; s < 6; s++) {
            int kl = s * 32 + lane;
            if (kbase + kl < KLAT) orow[kl] = srow[kl];
        }
    }

    // peers may still be reading our lm/ls — hold smem until both are done
    CLUSTER_SYNC();
    #undef STAGE_A
    #undef STAGE_B
}

// ---------------------------------------------------------------------------
// Final reduce (lean 256-thread version): out[0] = -ll
// ---------------------------------------------------------------------------
__global__ void final_kernel(const float* __restrict__ beta,
                             float* __restrict__ out, int Nrows, int nblocks) {
    __shared__ double red[256];
    int tid = threadIdx.x;
    int lane = tid & 31;
    double s = 0.0;
    for (int i = tid; i < nblocks; i += 256) s += g_partial[i];
    red[tid] = s;
    __syncthreads();
    if (tid < 32) {
        double a = red[tid];
        #pragma unroll
        for (int i = 1; i < 8; i++) a += red[tid + i * 32];
        #pragma unroll
        for (int o = 16; o > 0; o >>= 1)
            a += __shfl_xor_sync(0xffffffffu, a, o);
        if (lane == 0) {
            double b = (double)beta[0];
            double cst = 256.0 * log(b / (2.0 * M_PI)) - log(360.0);
            double ll = ((double)Nrows * cst + a) / (double)Nrows;
            out[0] = (float)(-ll);
        }
    }
}

// ---------------------------------------------------------------------------
extern "C" void kernel_launch(void* const* d_in, const int* in_sizes, int n_in,
                              void* d_out, int out_size) {
    const float* t    = (const float*)d_in[0];
    const float* W    = (const float*)d_in[1];
    const float* beta = (const float*)d_in[2];
    float* out = (float*)d_out;

    int N = in_sizes[0] / DIM;                                  // 131072
    long long off = (long long)out_size - (long long)N * KLAT;  // scalar slot first
    if (off < 0) off = 0;

    static int smem_set = 0;
    if (!smem_set) {
        cudaFuncSetAttribute(gtm_mma_kernel,
                             cudaFuncAttributeMaxDynamicSharedMemorySize, SMEM_TOTAL);
        smem_set = 1;
    }

    phi_kernel<<<(KLAT * MRBF + 255) / 256, 256>>>();
    y_kernel<<<KP, 128>>>(W);
    int nrowblk = N / TM;        // 2048
    gtm_mma_kernel<<<nrowblk * 2, NTHREADS, SMEM_TOTAL>>>(t, beta, out, off);
    final_kernel<<<1, 256>>>(beta, out, N, nrowblk);
}